// round 1
// baseline (speedup 1.0000x reference)
#include <cuda_runtime.h>
#include <math.h>

// ---------------------------------------------------------------------------
// YoloV1Loss on GB300
// rows = B*S = 16384*49 = 802816, each row = 30 fp32 (predictions & targets)
//
// Phase 1: per-block count of coord_mask (targets[:,4]==1)
// Phase 2: single-block scan -> exclusive block prefixes + n_obj, zero acc
// Phase 3: single full-data pass: per-row loss contribution, block reduce,
//          atomicAdd into __device__ double
// Phase 4: cast to fp32 scalar output
// ---------------------------------------------------------------------------

#define ROWS_PER_BLOCK 256
#define MAX_BLOCKS 8192
#define NCLS 20

__device__ int    g_counts[MAX_BLOCKS];
__device__ int    g_prefix[MAX_BLOCKS];
__device__ int    g_nobj;
__device__ double g_acc;

// ---------------- Phase 1: mask counts per block ----------------
__global__ void yolo_count(const float* __restrict__ t, int nrows) {
    int row = blockIdx.x * ROWS_PER_BLOCK + threadIdx.x;
    bool cm = false;
    if (row < nrows) cm = (t[(size_t)row * 30 + 4] == 1.0f);
    unsigned bal = __ballot_sync(0xffffffffu, cm);
    __shared__ int wsum[ROWS_PER_BLOCK / 32];
    if ((threadIdx.x & 31) == 0) wsum[threadIdx.x >> 5] = __popc(bal);
    __syncthreads();
    if (threadIdx.x == 0) {
        int s = 0;
#pragma unroll
        for (int i = 0; i < ROWS_PER_BLOCK / 32; i++) s += wsum[i];
        g_counts[blockIdx.x] = s;
    }
}

// ---------------- Phase 2: scan of block counts (single block) ----------------
__global__ void yolo_scan(int nblocks) {
    __shared__ int sm[1024];
    int carry = 0;
    for (int base = 0; base < nblocks; base += 1024) {
        int i = base + threadIdx.x;
        int v = (i < nblocks) ? g_counts[i] : 0;
        sm[threadIdx.x] = v;
        __syncthreads();
#pragma unroll
        for (int off = 1; off < 1024; off <<= 1) {
            int x = (threadIdx.x >= (unsigned)off) ? sm[threadIdx.x - off] : 0;
            __syncthreads();
            sm[threadIdx.x] += x;
            __syncthreads();
        }
        if (i < nblocks) g_prefix[i] = carry + sm[threadIdx.x] - v;  // exclusive
        carry += sm[1023];
        __syncthreads();
    }
    if (threadIdx.x == 0) {
        g_nobj = carry;
        g_acc  = 0.0;
    }
}

// ---------------- Phase 3: main loss pass ----------------
__global__ void yolo_main(const float* __restrict__ p, const float* __restrict__ t,
                          int nrows) {
    extern __shared__ float smem[];
    float* ps = smem;                         // ROWS_PER_BLOCK*30 floats
    float* ts = smem + ROWS_PER_BLOCK * 30;   // ROWS_PER_BLOCK*30 floats

    const int bid  = blockIdx.x;
    const int tid  = threadIdx.x;
    const int row0 = bid * ROWS_PER_BLOCK;
    const int rows = min(ROWS_PER_BLOCK, nrows - row0);
    const size_t base = (size_t)row0 * 30;
    const int nflt = rows * 30;

    // coalesced staging (float4 fast path: base is multiple of 7680 floats)
    if ((nflt & 3) == 0) {
        const float4* pg = (const float4*)(p + base);
        const float4* tg = (const float4*)(t + base);
        float4* p4 = (float4*)ps;
        float4* t4 = (float4*)ts;
        const int n4 = nflt >> 2;
        for (int i = tid; i < n4; i += ROWS_PER_BLOCK) {
            p4[i] = pg[i];
            t4[i] = tg[i];
        }
    } else {
        for (int i = tid; i < nflt; i += ROWS_PER_BLOCK) {
            ps[i] = p[base + i];
            ts[i] = t[base + i];
        }
    }
    __syncthreads();

    const bool inrange = (tid < rows);
    const float* pr = ps + tid * 30;
    const float* tr = ts + tid * 30;

    const float conf = inrange ? tr[4] : -1.0f;
    const bool  cm   = (conf == 1.0f);

    // in-block inclusive prefix of mask
    unsigned bal = __ballot_sync(0xffffffffu, cm);
    const int lane = tid & 31;
    const int wid  = tid >> 5;
    unsigned le_mask;
    asm("mov.u32 %0, %%lanemask_le;" : "=r"(le_mask));
    const int inc = __popc(bal & le_mask);  // inclusive within warp

    __shared__ int wtot[ROWS_PER_BLOCK / 32];
    if (lane == 31) wtot[wid] = __popc(bal);
    __syncthreads();
    int woff = 0;
#pragma unroll
    for (int i = 0; i < ROWS_PER_BLOCK / 32; i++)
        if (i < wid) woff += wtot[i];

    const int rank = g_prefix[bid] + woff + inc;  // global inclusive rank
    const int half = g_nobj >> 1;                  // n_obj // 2

    float contrib = 0.0f;
    if (inrange) {
        if (conf == 0.0f) {
            // noobj loss: LAMBDA_NOOBJ * ((p4-t4)^2 + (p9-t9)^2)
            float d0 = pr[4] - tr[4];
            float d1 = pr[9] - tr[9];
            contrib = 0.5f * (d0 * d0 + d1 * d1);
        } else if (cm && rank <= half) {
            const float C = 1.0f / 7.0f;  // CELL_SILE
            // target box (squared coords)
            float tb0 = tr[0] * tr[0], tb1 = tr[1] * tr[1];
            float tb2 = tr[2] * tr[2], tb3 = tr[3] * tr[3];
            float tax = tb0 * C - tb2, tay = tb1 * C - tb3;
            float tbx = tax * C + tb2, tby = tay * C + tb3;
            float at  = (tbx - tax) * (tby - tay);

            float iou0 = 0.0f, iou1 = 0.0f;
#pragma unroll
            for (int b = 0; b < 2; b++) {
                float x = pr[b * 5 + 0], y = pr[b * 5 + 1];
                float w = pr[b * 5 + 2], h = pr[b * 5 + 3];
                float ax = x * C - w, ay = y * C - h;
                float bx = ax * C + w, by = ay * C + h;
                float ltx = fmaxf(ax, tax), lty = fmaxf(ay, tay);
                float rbx = fminf(bx, tbx), rby = fminf(by, tby);
                float iw = fmaxf(rbx - ltx, 0.0f);
                float ih = fmaxf(rby - lty, 0.0f);
                float inter = iw * ih;
                float ap = (bx - ax) * (by - ay);
                float iou = inter / (ap + at - inter);
                if (b == 0) iou0 = iou; else iou1 = iou;
            }
            // numpy argmax semantics (NaN is max, first occurrence wins)
            int idx;
            if (isnan(iou0))       idx = 0;
            else if (isnan(iou1))  idx = 1;
            else                   idx = (iou1 > iou0) ? 1 : 0;

            const int ob = idx * 5;
            float s0 = pr[ob + 0] - tr[0];
            float s1 = pr[ob + 1] - tr[1];
            float s2 = pr[ob + 2] - tr[2];
            float s3 = pr[ob + 3] - tr[3];

            // class argmax over t[10:30] (first strict max)
            float best = tr[10];
            int oi = 0;
#pragma unroll
            for (int j = 1; j < NCLS; j++) {
                float v = tr[10 + j];
                if (v > best) { best = v; oi = j; }
            }
            float clv = pr[10 + oi] - 1.0f;

            // LAMBDA_COORD * (center + xywh + conf_l + cls_l), conf_l == cls_l
            contrib = 5.0f * (s0 * s0 + s1 * s1 + s2 * s2 + s3 * s3 + 2.0f * clv * clv);
        }
    }

    // block reduce (fp32 within block, fp64 across blocks)
#pragma unroll
    for (int off = 16; off > 0; off >>= 1)
        contrib += __shfl_down_sync(0xffffffffu, contrib, off);

    __shared__ float wred[ROWS_PER_BLOCK / 32];
    if (lane == 0) wred[wid] = contrib;
    __syncthreads();
    if (tid == 0) {
        float s = 0.0f;
#pragma unroll
        for (int i = 0; i < ROWS_PER_BLOCK / 32; i++) s += wred[i];
        atomicAdd(&g_acc, (double)s);
    }
}

// ---------------- Phase 4: finalize ----------------
__global__ void yolo_final(float* out) {
    out[0] = (float)g_acc;
}

// ---------------------------------------------------------------------------
extern "C" void kernel_launch(void* const* d_in, const int* in_sizes, int n_in,
                              void* d_out, int out_size) {
    const float* p = (const float*)d_in[0];  // predictions
    const float* t = (const float*)d_in[1];  // targets

    const int nrows   = in_sizes[0] / 30;
    const int nblocks = (nrows + ROWS_PER_BLOCK - 1) / ROWS_PER_BLOCK;

    const int smem_bytes = 2 * ROWS_PER_BLOCK * 30 * (int)sizeof(float);  // 61440
    cudaFuncSetAttribute(yolo_main, cudaFuncAttributeMaxDynamicSharedMemorySize,
                         smem_bytes);

    yolo_count<<<nblocks, ROWS_PER_BLOCK>>>(t, nrows);
    yolo_scan<<<1, 1024>>>(nblocks);
    yolo_main<<<nblocks, ROWS_PER_BLOCK, smem_bytes>>>(p, t, nrows);
    yolo_final<<<1, 1>>>((float*)d_out);
}

// round 2
// speedup vs baseline: 1.0818x; 1.0818x over previous
#include <cuda_runtime.h>
#include <math.h>

// ---------------------------------------------------------------------------
// YoloV1Loss, 2-kernel plan:
//  K1 yolo_main : one pass over cols 0..9 of p,t (64B aligned chunk per row,
//                 coalesced float4 -> smem), lazy global gathers of t[10:30]
//                 + p[10+oi] for coord rows only. Emits per-block: count,
//                 noobj fp32 sum, rank-compacted coord contributions.
//  K2 yolo_reduce: 444 blocks; each derives its exclusive prefix from the
//                 3136 counts (L2), applies the global rank<=n_obj/2 gate,
//                 reduces in double, atomicAdd; last block writes output.
// ---------------------------------------------------------------------------

#define RPB   256
#define MAXB  4096
#define NB2   444
#define PAD   17     // smem floats per row (odd -> conflict-free compute reads)
#define NCLS  20

__device__ int      g_counts[MAXB];
__device__ float    g_noobj[MAXB];
__device__ float    g_contrib[MAXB * RPB];   // rank-compacted per block
__device__ double   g_acc;
__device__ unsigned g_done;

// ---------------- K1: main pass ----------------
__global__ void __launch_bounds__(RPB) yolo_main(const float* __restrict__ p,
                                                 const float* __restrict__ t,
                                                 int nrows) {
    __shared__ float ps[RPB * PAD];
    __shared__ float tsd[RPB * PAD];
    __shared__ int   wtot[RPB / 32];
    __shared__ float wred[RPB / 32];

    const int tid  = threadIdx.x;
    const int bid  = blockIdx.x;
    const int row0 = bid * RPB;

    if (bid == 0 && tid == 0) { g_acc = 0.0; g_done = 0u; }

    // Stage the aligned 64B chunk covering floats [row*30, row*30+10) for
    // both arrays. chunk = (row*30) & ~7 ; chunk+16 <= nrows*30 always.
    for (int j = tid; j < RPB * 4; j += RPB) {
        const int r    = j >> 2;
        const int part = j & 3;
        const int grow = row0 + r;
        if (grow < nrows) {
            const int chunkf = (grow * 30) & ~7;
            const float4 pv = *(const float4*)(p + chunkf + part * 4);
            const float4 tv = *(const float4*)(t + chunkf + part * 4);
            const int si = r * PAD + part * 4;
            ps[si + 0] = pv.x; ps[si + 1] = pv.y;
            ps[si + 2] = pv.z; ps[si + 3] = pv.w;
            tsd[si + 0] = tv.x; tsd[si + 1] = tv.y;
            tsd[si + 2] = tv.z; tsd[si + 3] = tv.w;
        }
    }
    __syncthreads();

    const int  grow    = row0 + tid;
    const bool inrange = (grow < nrows);
    const int  off     = (grow * 30) & 7;
    const float* pr = ps  + tid * PAD + off;   // pr[c] == p[grow*30 + c], c<10
    const float* tr = tsd + tid * PAD + off;

    const float conf = inrange ? tr[4] : -1.0f;
    const bool  cm   = (conf == 1.0f);

    // in-block inclusive rank of coord rows
    const unsigned bal  = __ballot_sync(0xffffffffu, cm);
    const int      lane = tid & 31;
    const int      wid  = tid >> 5;
    unsigned le_mask;
    asm("mov.u32 %0, %%lanemask_le;" : "=r"(le_mask));
    const int inc = __popc(bal & le_mask);
    if (lane == 31) wtot[wid] = __popc(bal);
    __syncthreads();
    int woff = 0, ctot = 0;
#pragma unroll
    for (int i = 0; i < RPB / 32; i++) {
        int c = wtot[i];
        if (i < wid) woff += c;
        ctot += c;
    }

    // noobj contribution (fp32)
    float nv = 0.0f;
    if (inrange && conf == 0.0f) {
        const float d0 = pr[4] - tr[4];
        const float d1 = pr[9] - tr[9];
        nv = 0.5f * (d0 * d0 + d1 * d1);
    }

    // coord contribution for ALL coord rows (gate applied in K2)
    if (cm) {
        const float C = 1.0f / 7.0f;
        const float tb0 = tr[0] * tr[0], tb1 = tr[1] * tr[1];
        const float tb2 = tr[2] * tr[2], tb3 = tr[3] * tr[3];
        const float tax = tb0 * C - tb2, tay = tb1 * C - tb3;
        const float tbx = tax * C + tb2, tby = tay * C + tb3;
        const float at  = (tbx - tax) * (tby - tay);

        float iou0 = 0.0f, iou1 = 0.0f;
#pragma unroll
        for (int b = 0; b < 2; b++) {
            const float x = pr[b * 5 + 0], y = pr[b * 5 + 1];
            const float w = pr[b * 5 + 2], h = pr[b * 5 + 3];
            const float ax = x * C - w,  ay = y * C - h;
            const float bx = ax * C + w, by = ay * C + h;
            const float iw = fmaxf(fminf(bx, tbx) - fmaxf(ax, tax), 0.0f);
            const float ih = fmaxf(fminf(by, tby) - fmaxf(ay, tay), 0.0f);
            const float inter = iw * ih;
            const float ap = (bx - ax) * (by - ay);
            const float iou = inter / (ap + at - inter);
            if (b == 0) iou0 = iou; else iou1 = iou;
        }
        int idx;
        if (isnan(iou0))      idx = 0;   // numpy argmax: NaN wins, first occ.
        else if (isnan(iou1)) idx = 1;
        else                  idx = (iou1 > iou0) ? 1 : 0;

        const int ob = idx * 5;
        const float s0 = pr[ob + 0] - tr[0];
        const float s1 = pr[ob + 1] - tr[1];
        const float s2 = pr[ob + 2] - tr[2];
        const float s3 = pr[ob + 3] - tr[3];

        // lazy gather: t[grow, 10:30] (10x float2, 8B aligned), argmax first-max
        const float* tg = t + grow * 30 + 10;
        float best = -1.0f;
        int   oi   = 0;
#pragma unroll
        for (int j = 0; j < NCLS / 2; j++) {
            const float2 v = *(const float2*)(tg + 2 * j);
            if (v.x > best) { best = v.x; oi = 2 * j; }
            if (v.y > best) { best = v.y; oi = 2 * j + 1; }
        }
        const float clv = __ldg(p + grow * 30 + 10 + oi) - 1.0f;

        const float cv = 5.0f * (s0 * s0 + s1 * s1 + s2 * s2 + s3 * s3 +
                                 2.0f * clv * clv);
        g_contrib[bid * RPB + (woff + inc - 1)] = cv;
    }

    // block reduce noobj (fp32 within block)
#pragma unroll
    for (int o = 16; o > 0; o >>= 1)
        nv += __shfl_down_sync(0xffffffffu, nv, o);
    if (lane == 0) wred[wid] = nv;
    __syncthreads();
    if (tid == 0) {
        float s = 0.0f;
#pragma unroll
        for (int i = 0; i < RPB / 32; i++) s += wred[i];
        g_noobj[bid]  = s;
        g_counts[bid] = ctot;
    }
}

// ---------------- K2: gated reduce + finalize ----------------
__global__ void __launch_bounds__(256) yolo_reduce(float* __restrict__ out,
                                                   int nblocks) {
    const int tid = threadIdx.x;
    const int b2  = blockIdx.x;
    const int per = (nblocks + NB2 - 1) / NB2;
    const int b0  = b2 * per;
    const int b1  = min(b0 + per, nblocks);

    __shared__ int s_tot[256 / 32];
    __shared__ int s_pre[256 / 32];
    __shared__ int sh_tot, sh_pre;

    // total count + exclusive prefix before b0 (counts live in L2)
    int myTot = 0, myPre = 0;
    for (int i = tid; i < nblocks; i += 256) {
        const int c = g_counts[i];
        myTot += c;
        if (i < b0) myPre += c;
    }
#pragma unroll
    for (int o = 16; o > 0; o >>= 1) {
        myTot += __shfl_down_sync(0xffffffffu, myTot, o);
        myPre += __shfl_down_sync(0xffffffffu, myPre, o);
    }
    if ((tid & 31) == 0) { s_tot[tid >> 5] = myTot; s_pre[tid >> 5] = myPre; }
    __syncthreads();
    if (tid == 0) {
        int a = 0, b = 0;
#pragma unroll
        for (int i = 0; i < 256 / 32; i++) { a += s_tot[i]; b += s_pre[i]; }
        sh_tot = a; sh_pre = b;
    }
    __syncthreads();
    const int half = sh_tot >> 1;   // n_obj // 2
    int pb = sh_pre;

    double acc = 0.0;
    for (int b = b0; b < b1; b++) {
        const int cnt  = g_counts[b];
        const int take = min(cnt, max(0, half - pb));   // rank pb+i+1 <= half
        const float* cb = g_contrib + b * RPB;
        for (int i = tid; i < take; i += 256) acc += (double)cb[i];
        if (tid == (b & 255)) acc += (double)g_noobj[b];
        pb += cnt;
    }

    // block reduce double
    __shared__ double s_d[256 / 32];
#pragma unroll
    for (int o = 16; o > 0; o >>= 1)
        acc += __shfl_down_sync(0xffffffffu, acc, o);
    if ((tid & 31) == 0) s_d[tid >> 5] = acc;
    __syncthreads();
    if (tid == 0) {
        double s = 0.0;
#pragma unroll
        for (int i = 0; i < 256 / 32; i++) s += s_d[i];
        atomicAdd(&g_acc, s);
        __threadfence();
        const unsigned old = atomicAdd(&g_done, 1u);
        if (old == (unsigned)(gridDim.x - 1)) {
            out[0] = (float)atomicAdd(&g_acc, 0.0);   // atomic read-back
        }
    }
}

// ---------------------------------------------------------------------------
extern "C" void kernel_launch(void* const* d_in, const int* in_sizes, int n_in,
                              void* d_out, int out_size) {
    const float* p = (const float*)d_in[0];
    const float* t = (const float*)d_in[1];

    const int nrows   = in_sizes[0] / 30;
    const int nblocks = (nrows + RPB - 1) / RPB;

    yolo_main<<<nblocks, RPB>>>(p, t, nrows);
    yolo_reduce<<<NB2, 256>>>((float*)d_out, nblocks);
}